// round 16
// baseline (speedup 1.0000x reference)
#include <cuda_runtime.h>
#include <cuda_bf16.h>
#include <cstddef>
#include <cstdint>

#define N_NODES 100000
#define N_EDGES 3200000
#define NITER 8                 // 128-edge tiles per block
#define GRID_EDGE 3125          // 3125 * 8 * 128 = 3,200,000

typedef unsigned long long ull;

// Per-node precomputed projections (static device scratch — allowed).
__device__ float g_A[(size_t)N_NODES * 32];  // be1 + x@We1[0:32,:]
__device__ float g_B[(size_t)N_NODES * 32];  // x@We1[32:64,:]
__device__ float g_C[(size_t)N_NODES * 64];  // bn1 + x@Wn1[0:32,:]

// Small weights in constant memory -> warp-uniform LDCU, zero L1 wavefronts.
__constant__ float c_We1t[6 * 32];   // We1 rows 64..69
__constant__ float c_We2[32 * 6];
__constant__ float c_Wn1t[6 * 64];   // Wn1 rows 32..37
__constant__ float c_be2[6];
__constant__ float c_bn2[32];

// ---------------- packed f32x2 helpers ----------------
__device__ __forceinline__ ull pack2(float a, float b) {
    ull r; asm("mov.b64 %0, {%1, %2};" : "=l"(r) : "f"(a), "f"(b)); return r;
}
__device__ __forceinline__ void unpack2(ull v, float& a, float& b) {
    asm("mov.b64 {%0, %1}, %2;" : "=f"(a), "=f"(b) : "l"(v));
}
__device__ __forceinline__ ull fma2(ull a, ull b, ull c) {
    ull d; asm("fma.rn.f32x2 %0, %1, %2, %3;" : "=l"(d) : "l"(a), "l"(b), "l"(c)); return d;
}
__device__ __forceinline__ ull add2(ull a, ull b) {
    ull d; asm("add.rn.f32x2 %0, %1, %2;" : "=l"(d) : "l"(a), "l"(b)); return d;
}
__device__ __forceinline__ void relu2(ull v, float& a, float& b) {
    unpack2(v, a, b);
    a = fmaxf(a, 0.0f);
    b = fmaxf(b, 0.0f);
}

__device__ __forceinline__ uint32_t smem_u32(const void* p) {
    uint32_t a;
    asm("{ .reg .u64 tmp; cvta.to.shared.u64 tmp, %1; cvt.u32.u64 %0, tmp; }"
        : "=r"(a) : "l"(p));
    return a;
}

// ---------------- cp.async helpers (sm_80 PTX, safe at compute_103) -------
__device__ __forceinline__ void cp_async16(uint32_t saddr, const void* gaddr) {
    asm volatile("cp.async.cg.shared.global [%0], [%1], 16;"
                 :: "r"(saddr), "l"(gaddr) : "memory");
}
__device__ __forceinline__ void cp_commit() {
    asm volatile("cp.async.commit_group;" ::: "memory");
}
__device__ __forceinline__ void cp_wait0() {
    asm volatile("cp.async.wait_group 0;" ::: "memory");
}

// ---------------- warp MMA helpers (sm_80-era PTX, safe at compute_103) ----
__device__ __forceinline__ void ldsm_x4(uint32_t* r, uint32_t addr) {
    asm volatile("ldmatrix.sync.aligned.m8n8.x4.shared.b16 {%0,%1,%2,%3}, [%4];"
                 : "=r"(r[0]), "=r"(r[1]), "=r"(r[2]), "=r"(r[3]) : "r"(addr));
}
__device__ __forceinline__ void mma_bf16(float* c, const uint32_t* a,
                                         uint32_t b0, uint32_t b1) {
    asm volatile(
        "mma.sync.aligned.m16n8k16.row.col.f32.bf16.bf16.f32 "
        "{%0,%1,%2,%3}, {%4,%5,%6,%7}, {%8,%9}, {%0,%1,%2,%3};"
        : "+f"(c[0]), "+f"(c[1]), "+f"(c[2]), "+f"(c[3])
        : "r"(a[0]), "r"(a[1]), "r"(a[2]), "r"(a[3]), "r"(b0), "r"(b1));
}

// ---------------- SMEM layout (dynamic): per-warp buffers only ------------
// per-warp buffer (17920B):
//   GA: 32 rows x 144B (gather A+B fused; then h2-hi mma plane; then nm rows)
//   GB: 32 rows x 144B (h2-lo mma plane)
//   GC: 32 rows x 272B (dedicated pipelined cp.async C buffer)
#define W_GA 0
#define W_GB 4608
#define W_GC 9216
#define W_SIZE 17920
#define A_STRIDE 144
#define C_STRIDE 272
#define SM_TOTAL (4 * W_SIZE)    // 71680 bytes -> 3 CTAs/SM

// ================= precompute kernel: per-node projections =================
// Two register phases (A/B then C) to halve live accumulators -> higher occ.
__global__ void __launch_bounds__(256) mpn_precompute_kernel(
    const float* __restrict__ x_node,
    const float* __restrict__ We1, const float* __restrict__ be1,
    const float* __restrict__ Wn1, const float* __restrict__ bn1)
{
    __shared__ __align__(16) float sW1[64 * 32];
    __shared__ __align__(16) float sWn[32 * 64];
    __shared__ __align__(16) float sbe1[32];
    __shared__ __align__(16) float sbn1[64];

    const int t = threadIdx.x;
    for (int i = t; i < 64 * 32; i += 256) sW1[i] = We1[i];
    for (int i = t; i < 32 * 64; i += 256) sWn[i] = Wn1[i];
    if (t < 32) sbe1[t] = be1[t];
    if (t < 64) sbn1[t] = bn1[t];
    __syncthreads();

    const int n = blockIdx.x * 256 + t;
    if (n >= N_NODES) return;

    float x[32];
    {
        const float4* px = reinterpret_cast<const float4*>(x_node + (size_t)n * 32);
#pragma unroll
        for (int i = 0; i < 8; i++) {
            float4 v = px[i];
            x[4*i] = v.x; x[4*i+1] = v.y; x[4*i+2] = v.z; x[4*i+3] = v.w;
        }
    }

    // ---- phase 1: A and B ----
    {
        ull accA[16], accB[16];
#pragma unroll
        for (int j = 0; j < 16; j++) {
            accA[j] = *reinterpret_cast<const ull*>(sbe1 + 2 * j);
            accB[j] = pack2(0.0f, 0.0f);
        }
#pragma unroll
        for (int i = 0; i < 32; i++) {
            ull ev = pack2(x[i], x[i]);
            const ulonglong2* wa = reinterpret_cast<const ulonglong2*>(sW1 + i * 32);
            const ulonglong2* wb = reinterpret_cast<const ulonglong2*>(sW1 + (32 + i) * 32);
#pragma unroll
            for (int k = 0; k < 8; k++) {
                ulonglong2 w = wa[k];
                accA[2*k]   = fma2(ev, w.x, accA[2*k]);
                accA[2*k+1] = fma2(ev, w.y, accA[2*k+1]);
            }
#pragma unroll
            for (int k = 0; k < 8; k++) {
                ulonglong2 w = wb[k];
                accB[2*k]   = fma2(ev, w.x, accB[2*k]);
                accB[2*k+1] = fma2(ev, w.y, accB[2*k+1]);
            }
        }
        ulonglong2* pA = reinterpret_cast<ulonglong2*>(g_A + (size_t)n * 32);
        ulonglong2* pB = reinterpret_cast<ulonglong2*>(g_B + (size_t)n * 32);
#pragma unroll
        for (int k = 0; k < 8; k++) pA[k] = make_ulonglong2(accA[2*k], accA[2*k+1]);
#pragma unroll
        for (int k = 0; k < 8; k++) pB[k] = make_ulonglong2(accB[2*k], accB[2*k+1]);
    }

    // ---- phase 2: C ----
    {
        ull accC[32];
#pragma unroll
        for (int j = 0; j < 32; j++)
            accC[j] = *reinterpret_cast<const ull*>(sbn1 + 2 * j);
#pragma unroll
        for (int i = 0; i < 32; i++) {
            ull ev = pack2(x[i], x[i]);
            const ulonglong2* wc = reinterpret_cast<const ulonglong2*>(sWn + i * 64);
#pragma unroll
            for (int k = 0; k < 16; k++) {
                ulonglong2 w = wc[k];
                accC[2*k]   = fma2(ev, w.x, accC[2*k]);
                accC[2*k+1] = fma2(ev, w.y, accC[2*k+1]);
            }
        }
        ulonglong2* pC = reinterpret_cast<ulonglong2*>(g_C + (size_t)n * 64);
#pragma unroll
        for (int k = 0; k < 16; k++) pC[k] = make_ulonglong2(accC[2*k], accC[2*k+1]);
    }
}

// ======= edge kernel: pipelined C, fused A+B gather, layer-4 mma.sync =====
__global__ void __launch_bounds__(128, 3) mpn_edge_kernel(
    const float* __restrict__ x_edge,
    const int* __restrict__ src, const int* __restrict__ dst,
    const float* __restrict__ Wn2,
    float* __restrict__ out_nm, float* __restrict__ out_em)
{
    extern __shared__ char smem[];
    const uint32_t smem_base = smem_u32(smem);
    const int t = threadIdx.x;
    const int wid = t >> 5;
    const int lane = t & 31;

    // ---- hoist Wn2 B-fragments (bf16 hi/lo) into registers, once ----
    const int col = lane >> 2;          // n within 8-col group
    const int krow = lane & 3;          // k-pair row within quad
    uint32_t Bh[4][4][2], Bl[4][4][2];
#pragma unroll
    for (int kt = 0; kt < 4; kt++) {
#pragma unroll
        for (int nt = 0; nt < 4; nt++) {
            int n = nt * 8 + col;
            int kp0 = kt * 8 + krow;
            int kp1 = kp0 + 4;
            float w00 = Wn2[(2 * kp0) * 32 + n];
            float w01 = Wn2[(2 * kp0 + 1) * 32 + n];
            float w10 = Wn2[(2 * kp1) * 32 + n];
            float w11 = Wn2[(2 * kp1 + 1) * 32 + n];
            uint32_t u00 = __float_as_uint(w00), u01 = __float_as_uint(w01);
            uint32_t u10 = __float_as_uint(w10), u11 = __float_as_uint(w11);
            Bh[kt][nt][0] = __byte_perm(u00, u01, 0x7632);
            Bh[kt][nt][1] = __byte_perm(u10, u11, 0x7632);
            float l00 = w00 - __uint_as_float(u00 & 0xFFFF0000u);
            float l01 = w01 - __uint_as_float(u01 & 0xFFFF0000u);
            float l10 = w10 - __uint_as_float(u10 & 0xFFFF0000u);
            float l11 = w11 - __uint_as_float(u11 & 0xFFFF0000u);
            uint32_t p0, p1;
            asm("cvt.rn.bf16x2.f32 %0, %1, %2;" : "=r"(p0) : "f"(l01), "f"(l00));
            asm("cvt.rn.bf16x2.f32 %0, %1, %2;" : "=r"(p1) : "f"(l11), "f"(l10));
            Bl[kt][nt][0] = p0;
            Bl[kt][nt][1] = p1;
        }
    }

    // epilogue bias pairs: cols nt*8 + krow*2, +1
    float2 bias[4];
#pragma unroll
    for (int nt = 0; nt < 4; nt++)
        bias[nt] = make_float2(c_bn2[nt * 8 + krow * 2], c_bn2[nt * 8 + krow * 2 + 1]);

    char* wbuf = smem + wid * W_SIZE;
    const uint32_t wbuf_u = smem_base + wid * W_SIZE;
    const uint32_t a_hi_base = wbuf_u + W_GA;
    const uint32_t a_lo_base = wbuf_u + W_GB;
    const uint32_t lds_lane_off = (uint32_t)(lane & 15) * A_STRIDE + (uint32_t)(lane >> 4) * 16;
    const int sub = lane >> 3;          // 0..3 : which edge within a gather instr
    const int qe  = lane & 7;           // 0..7 : 16B chunk within a 128B row

    const int e_base = blockIdx.x * NITER * 128 + wid * 32 + lane;
    int s_cur = src[e_base];
    int d_cur = dst[e_base];

    // ---- prologue: fire C for iteration 0 ----
#pragma unroll
    for (int j = 0; j < 16; j++) {
        int c = 4 * j + sub;
        int eloc = c >> 1, half = c & 1;
        int dn = __shfl_sync(0xFFFFFFFFu, d_cur, eloc);
        cp_async16(wbuf_u + W_GC + eloc * C_STRIDE + half * 128 + qe * 16,
                   g_C + (size_t)dn * 64 + half * 32 + qe * 4);
    }
    cp_commit();

    for (int it = 0; it < NITER; it++) {
        const int e = e_base + it * 128;
        const int s = s_cur;
        const int d = d_cur;

        // ======== A+B fused gather (consumed at layer 1) ========
#pragma unroll
        for (int j = 0; j < 8; j++) {
            int eloc = 4 * j + sub;
            int dn = __shfl_sync(0xFFFFFFFFu, d, eloc);
            int sn = __shfl_sync(0xFFFFFFFFu, s, eloc);
            ulonglong2 va = *reinterpret_cast<const ulonglong2*>(g_A + (size_t)dn * 32 + qe * 4);
            ulonglong2 vb = *reinterpret_cast<const ulonglong2*>(g_B + (size_t)sn * 32 + qe * 4);
            ulonglong2 r;
            r.x = add2(va.x, vb.x);
            r.y = add2(va.y, vb.y);
            *reinterpret_cast<ulonglong2*>(wbuf + W_GA + eloc * A_STRIDE + qe * 16) = r;
        }

        // xe load + next-iter index prefetch (latency off critical path)
        float xe[6];
        {
            const float2* pe = reinterpret_cast<const float2*>(x_edge + (size_t)e * 6);
            float2 a = pe[0], b = pe[1], c = pe[2];
            xe[0]=a.x; xe[1]=a.y; xe[2]=b.x; xe[3]=b.y; xe[4]=c.x; xe[5]=c.y;
        }
        int s_nxt = 0, d_nxt = 0;
        if (it + 1 < NITER) {
            s_nxt = src[e + 128];
            d_nxt = dst[e + 128];
        }
        __syncwarp();

        // ======== layer 1: acc1 = (A[d]+B[s]) + xe @ We1[64:70] ========
        ull acc1[16];
        {
            const ulonglong2* ra = reinterpret_cast<const ulonglong2*>(wbuf + W_GA + lane * A_STRIDE);
#pragma unroll
            for (int k = 0; k < 8; k++) {
                ulonglong2 a = ra[k];
                acc1[2*k]   = a.x;
                acc1[2*k+1] = a.y;
            }
        }
#pragma unroll
        for (int i = 0; i < 6; i++) {
            ull ev = pack2(xe[i], xe[i]);
            const ulonglong2* w = reinterpret_cast<const ulonglong2*>(c_We1t + i * 32);
#pragma unroll
            for (int k = 0; k < 8; k++) {
                ulonglong2 wp = w[k];
                acc1[2*k]   = fma2(ev, wp.x, acc1[2*k]);
                acc1[2*k+1] = fma2(ev, wp.y, acc1[2*k+1]);
            }
        }
        float h1[32];
#pragma unroll
        for (int j = 0; j < 16; j++) relu2(acc1[j], h1[2*j], h1[2*j+1]);

        // ======== layer 2: em = relu(h1 @ We2 + be2), 6 accumulator chains ===
        ull acc2a[3], acc2b[3];
#pragma unroll
        for (int j = 0; j < 3; j++) {
            acc2a[j] = *reinterpret_cast<const ull*>(c_be2 + 2 * j);
            acc2b[j] = pack2(0.0f, 0.0f);
        }
#pragma unroll
        for (int i = 0; i < 16; i++) {
            const ull* wA = reinterpret_cast<const ull*>(c_We2 + i * 6);
            const ull* wB = reinterpret_cast<const ull*>(c_We2 + (16 + i) * 6);
            ull evA = pack2(h1[i], h1[i]);
            ull evB = pack2(h1[16 + i], h1[16 + i]);
            acc2a[0] = fma2(evA, wA[0], acc2a[0]);
            acc2a[1] = fma2(evA, wA[1], acc2a[1]);
            acc2a[2] = fma2(evA, wA[2], acc2a[2]);
            acc2b[0] = fma2(evB, wB[0], acc2b[0]);
            acc2b[1] = fma2(evB, wB[1], acc2b[1]);
            acc2b[2] = fma2(evB, wB[2], acc2b[2]);
        }
        float em[6];
#pragma unroll
        for (int j = 0; j < 3; j++) relu2(add2(acc2a[j], acc2b[j]), em[2*j], em[2*j+1]);
        {
            float2* po = reinterpret_cast<float2*>(out_em + (size_t)e * 6);
            po[0] = make_float2(em[0], em[1]);
            po[1] = make_float2(em[2], em[3]);
            po[2] = make_float2(em[4], em[5]);
        }

        // ======== wait for pipelined C, then layer 3 ========
        cp_wait0();
        __syncwarp();

        ull emv[6];
#pragma unroll
        for (int i = 0; i < 6; i++) emv[i] = pack2(em[i], em[i]);

        const char* rowC = wbuf + W_GC + lane * C_STRIDE;
        char* rowH = wbuf + W_GA + lane * A_STRIDE;
        char* rowL = wbuf + W_GB + lane * A_STRIDE;
#pragma unroll
        for (int c = 0; c < 4; c++) {
            ull acc3[8];
            const longlong2* pc = reinterpret_cast<const longlong2*>(rowC + c * 64);
#pragma unroll
            for (int k = 0; k < 4; k++) {
                longlong2 v = pc[k];
                acc3[2*k] = (ull)v.x; acc3[2*k+1] = (ull)v.y;
            }
#pragma unroll
            for (int i = 0; i < 6; i++) {
                const ulonglong2* w = reinterpret_cast<const ulonglong2*>(c_Wn1t + i * 64 + c * 16);
#pragma unroll
                for (int k = 0; k < 4; k++) {
                    ulonglong2 wp = w[k];
                    acc3[2*k]   = fma2(emv[i], wp.x, acc3[2*k]);
                    acc3[2*k+1] = fma2(emv[i], wp.y, acc3[2*k+1]);
                }
            }
            uint32_t hi[8], lo[8];
#pragma unroll
            for (int j = 0; j < 8; j++) {
                float a, b;
                relu2(acc3[j], a, b);
                uint32_t ua = __float_as_uint(a);
                uint32_t ub = __float_as_uint(b);
                float la = a - __uint_as_float(ua & 0xFFFF0000u);
                float lb = b - __uint_as_float(ub & 0xFFFF0000u);
                hi[j] = __byte_perm(ua, ub, 0x7632);
                asm("cvt.rn.bf16x2.f32 %0, %1, %2;" : "=r"(lo[j]) : "f"(lb), "f"(la));
            }
            reinterpret_cast<uint4*>(rowH)[2*c]     = make_uint4(hi[0], hi[1], hi[2], hi[3]);
            reinterpret_cast<uint4*>(rowH)[2*c + 1] = make_uint4(hi[4], hi[5], hi[6], hi[7]);
            reinterpret_cast<uint4*>(rowL)[2*c]     = make_uint4(lo[0], lo[1], lo[2], lo[3]);
            reinterpret_cast<uint4*>(rowL)[2*c + 1] = make_uint4(lo[4], lo[5], lo[6], lo[7]);
        }
        __syncwarp();   // all lanes done reading GC + h2 planes visible

        // ======== fire next iteration's C into the freed GC buffer ========
        if (it + 1 < NITER) {
#pragma unroll
            for (int j = 0; j < 16; j++) {
                int c = 4 * j + sub;
                int eloc = c >> 1, half = c & 1;
                int dn = __shfl_sync(0xFFFFFFFFu, d_nxt, eloc);
                cp_async16(wbuf_u + W_GC + eloc * C_STRIDE + half * 128 + qe * 16,
                           g_C + (size_t)dn * 64 + half * 32 + qe * 4);
            }
            cp_commit();
        }

        // ======== layer 4: C[32x32] = Ahi@(Bhi+Blo) + Alo@Bhi via mma.sync ===
        float acc[8][4];
#pragma unroll
        for (int f = 0; f < 8; f++) {
            acc[f][0] = 0.0f; acc[f][1] = 0.0f; acc[f][2] = 0.0f; acc[f][3] = 0.0f;
        }
#pragma unroll
        for (int kt = 0; kt < 4; kt++) {
            uint32_t a0[4], a1[4];
            ldsm_x4(a0, a_hi_base + lds_lane_off + kt * 32);
            ldsm_x4(a1, a_hi_base + lds_lane_off + 16 * A_STRIDE + kt * 32);
#pragma unroll
            for (int nt = 0; nt < 4; nt++) {
                mma_bf16(acc[nt],     a0, Bh[kt][nt][0], Bh[kt][nt][1]);
                mma_bf16(acc[nt],     a0, Bl[kt][nt][0], Bl[kt][nt][1]);
                mma_bf16(acc[4 + nt], a1, Bh[kt][nt][0], Bh[kt][nt][1]);
                mma_bf16(acc[4 + nt], a1, Bl[kt][nt][0], Bl[kt][nt][1]);
            }
        }
#pragma unroll
        for (int kt = 0; kt < 4; kt++) {
            uint32_t a0[4], a1[4];
            ldsm_x4(a0, a_lo_base + lds_lane_off + kt * 32);
            ldsm_x4(a1, a_lo_base + lds_lane_off + 16 * A_STRIDE + kt * 32);
#pragma unroll
            for (int nt = 0; nt < 4; nt++) {
                mma_bf16(acc[nt],     a0, Bh[kt][nt][0], Bh[kt][nt][1]);
                mma_bf16(acc[4 + nt], a1, Bh[kt][nt][0], Bh[kt][nt][1]);
            }
        }
        __syncwarp();   // ldsm reads of GA done before nm staging overwrites it

        // ======== epilogue: bias+relu -> GA rows, cooperative scatter ========
        const int r = lane >> 2;
        const int cb = krow * 2;
        char* nmbase = wbuf + W_GA;
#pragma unroll
        for (int mt = 0; mt < 2; mt++) {
#pragma unroll
            for (int nt = 0; nt < 4; nt++) {
                const float* a = acc[mt * 4 + nt];
                float v0 = fmaxf(a[0] + bias[nt].x, 0.0f);
                float v1 = fmaxf(a[1] + bias[nt].y, 0.0f);
                float v2 = fmaxf(a[2] + bias[nt].x, 0.0f);
                float v3 = fmaxf(a[3] + bias[nt].y, 0.0f);
                *reinterpret_cast<float2*>(nmbase + (mt * 16 + r) * A_STRIDE + (nt * 8 + cb) * 4)
                    = make_float2(v0, v1);
                *reinterpret_cast<float2*>(nmbase + (mt * 16 + r + 8) * A_STRIDE + (nt * 8 + cb) * 4)
                    = make_float2(v2, v3);
            }
        }
        __syncwarp();

#pragma unroll
        for (int j = 0; j < 8; j++) {
            int eloc = 4 * j + sub;
            int dn = __shfl_sync(0xFFFFFFFFu, d, eloc);
            float4 v = *reinterpret_cast<const float4*>(nmbase + eloc * A_STRIDE + qe * 16);
            asm volatile("red.global.add.v4.f32 [%0], {%1, %2, %3, %4};"
                         :: "l"(out_nm + (size_t)dn * 32 + qe * 4),
                            "f"(v.x), "f"(v.y), "f"(v.z), "f"(v.w) : "memory");
        }
        __syncwarp();   // nm reads done before next iter's A+B gather overwrites GA

        s_cur = s_nxt;
        d_cur = d_nxt;
    }
}

extern "C" void kernel_launch(void* const* d_in, const int* in_sizes, int n_in,
                              void* d_out, int out_size) {
    const float* x_node = (const float*)d_in[0];
    const float* x_edge = (const float*)d_in[1];
    const int*   src    = (const int*)d_in[2];
    const int*   dst    = (const int*)d_in[3];
    const float* We1    = (const float*)d_in[4];
    const float* be1    = (const float*)d_in[5];
    const float* We2    = (const float*)d_in[6];
    const float* be2    = (const float*)d_in[7];
    const float* Wn1    = (const float*)d_in[8];
    const float* bn1    = (const float*)d_in[9];
    const float* Wn2    = (const float*)d_in[10];
    const float* bn2    = (const float*)d_in[11];

    float* out    = (float*)d_out;
    float* out_nm = out;                        // [N_NODES, 32]
    float* out_em = out + (size_t)N_NODES * 32; // [N_EDGES, 6]

    cudaFuncSetAttribute(mpn_edge_kernel,
                         cudaFuncAttributeMaxDynamicSharedMemorySize, SM_TOTAL);

    // Stage small weights into constant memory (async D2D, graph-capturable).
    cudaMemcpyToSymbolAsync(c_We1t, We1 + 64 * 32, 6 * 32 * sizeof(float), 0,
                            cudaMemcpyDeviceToDevice);
    cudaMemcpyToSymbolAsync(c_We2, We2, 32 * 6 * sizeof(float), 0,
                            cudaMemcpyDeviceToDevice);
    cudaMemcpyToSymbolAsync(c_Wn1t, Wn1 + 32 * 64, 6 * 64 * sizeof(float), 0,
                            cudaMemcpyDeviceToDevice);
    cudaMemcpyToSymbolAsync(c_be2, be2, 6 * sizeof(float), 0,
                            cudaMemcpyDeviceToDevice);
    cudaMemcpyToSymbolAsync(c_bn2, bn2, 32 * sizeof(float), 0,
                            cudaMemcpyDeviceToDevice);

    cudaMemsetAsync(out_nm, 0, (size_t)N_NODES * 32 * sizeof(float));

    mpn_precompute_kernel<<<(N_NODES + 255) / 256, 256>>>(x_node, We1, be1, Wn1, bn1);

    mpn_edge_kernel<<<GRID_EDGE, 128, SM_TOTAL>>>(x_edge, src, dst, Wn2,
                                                  out_nm, out_em);
}

// round 17
// speedup vs baseline: 1.0553x; 1.0553x over previous
#include <cuda_runtime.h>
#include <cuda_bf16.h>
#include <cstddef>
#include <cstdint>

#define N_NODES 100000
#define N_EDGES 3200000
#define NITER 10                // 128-edge tiles per block
#define GRID_EDGE 2500          // 2500 * 10 * 128 = 3,200,000

typedef unsigned long long ull;

// Per-node precomputed projections (static device scratch — allowed).
__device__ float g_A[(size_t)N_NODES * 32];  // be1 + x@We1[0:32,:]
__device__ float g_B[(size_t)N_NODES * 32];  // x@We1[32:64,:]
__device__ float g_C[(size_t)N_NODES * 64];  // bn1 + x@Wn1[0:32,:]

// Small weights in constant memory -> warp-uniform LDCU, zero L1 wavefronts.
__constant__ float c_We1t[6 * 32];   // We1 rows 64..69
__constant__ float c_We2[32 * 6];
__constant__ float c_Wn1t[6 * 64];   // Wn1 rows 32..37
__constant__ float c_be2[6];
__constant__ float c_bn2[32];

// ---------------- packed f32x2 helpers ----------------
__device__ __forceinline__ ull pack2(float a, float b) {
    ull r; asm("mov.b64 %0, {%1, %2};" : "=l"(r) : "f"(a), "f"(b)); return r;
}
__device__ __forceinline__ void unpack2(ull v, float& a, float& b) {
    asm("mov.b64 {%0, %1}, %2;" : "=f"(a), "=f"(b) : "l"(v));
}
__device__ __forceinline__ ull fma2(ull a, ull b, ull c) {
    ull d; asm("fma.rn.f32x2 %0, %1, %2, %3;" : "=l"(d) : "l"(a), "l"(b), "l"(c)); return d;
}
__device__ __forceinline__ ull add2(ull a, ull b) {
    ull d; asm("add.rn.f32x2 %0, %1, %2;" : "=l"(d) : "l"(a), "l"(b)); return d;
}
__device__ __forceinline__ void relu2(ull v, float& a, float& b) {
    unpack2(v, a, b);
    a = fmaxf(a, 0.0f);
    b = fmaxf(b, 0.0f);
}

__device__ __forceinline__ uint32_t smem_u32(const void* p) {
    uint32_t a;
    asm("{ .reg .u64 tmp; cvta.to.shared.u64 tmp, %1; cvt.u32.u64 %0, tmp; }"
        : "=r"(a) : "l"(p));
    return a;
}

// ---------------- cp.async helpers (sm_80 PTX, safe at compute_103) -------
__device__ __forceinline__ void cp_async16(uint32_t saddr, const void* gaddr) {
    asm volatile("cp.async.cg.shared.global [%0], [%1], 16;"
                 :: "r"(saddr), "l"(gaddr) : "memory");
}
__device__ __forceinline__ void cp_commit() {
    asm volatile("cp.async.commit_group;" ::: "memory");
}
__device__ __forceinline__ void cp_wait0() {
    asm volatile("cp.async.wait_group 0;" ::: "memory");
}

// ---------------- warp MMA helpers (sm_80-era PTX, safe at compute_103) ----
__device__ __forceinline__ void ldsm_x4(uint32_t* r, uint32_t addr) {
    asm volatile("ldmatrix.sync.aligned.m8n8.x4.shared.b16 {%0,%1,%2,%3}, [%4];"
                 : "=r"(r[0]), "=r"(r[1]), "=r"(r[2]), "=r"(r[3]) : "r"(addr));
}
__device__ __forceinline__ void mma_bf16(float* c, const uint32_t* a,
                                         uint32_t b0, uint32_t b1) {
    asm volatile(
        "mma.sync.aligned.m16n8k16.row.col.f32.bf16.bf16.f32 "
        "{%0,%1,%2,%3}, {%4,%5,%6,%7}, {%8,%9}, {%0,%1,%2,%3};"
        : "+f"(c[0]), "+f"(c[1]), "+f"(c[2]), "+f"(c[3])
        : "r"(a[0]), "r"(a[1]), "r"(a[2]), "r"(a[3]), "r"(b0), "r"(b1));
}

// ---------------- SMEM layout (dynamic): per-warp buffers only ------------
// per-warp buffer (17920B):
//   GA: 32 rows x 144B (gather A+B fused; later h2-hi mma plane)
//   GB: 32 rows x 144B (h2-lo mma plane only)
//   GC: 32 rows x 272B (cp.async C; later nm staging rows x144)
#define W_GA 0
#define W_GB 4608
#define W_GC 9216
#define W_SIZE 17920
#define A_STRIDE 144
#define C_STRIDE 272
#define SM_TOTAL (4 * W_SIZE)    // 71680 bytes -> 3 CTAs/SM

// ================= precompute kernel: per-node projections =================
// Two register phases (A/B then C) to halve live accumulators -> higher occ.
__global__ void __launch_bounds__(256) mpn_precompute_kernel(
    const float* __restrict__ x_node,
    const float* __restrict__ We1, const float* __restrict__ be1,
    const float* __restrict__ Wn1, const float* __restrict__ bn1)
{
    __shared__ __align__(16) float sW1[64 * 32];
    __shared__ __align__(16) float sWn[32 * 64];
    __shared__ __align__(16) float sbe1[32];
    __shared__ __align__(16) float sbn1[64];

    const int t = threadIdx.x;
    for (int i = t; i < 64 * 32; i += 256) sW1[i] = We1[i];
    for (int i = t; i < 32 * 64; i += 256) sWn[i] = Wn1[i];
    if (t < 32) sbe1[t] = be1[t];
    if (t < 64) sbn1[t] = bn1[t];
    __syncthreads();

    const int n = blockIdx.x * 256 + t;
    if (n >= N_NODES) return;

    float x[32];
    {
        const float4* px = reinterpret_cast<const float4*>(x_node + (size_t)n * 32);
#pragma unroll
        for (int i = 0; i < 8; i++) {
            float4 v = px[i];
            x[4*i] = v.x; x[4*i+1] = v.y; x[4*i+2] = v.z; x[4*i+3] = v.w;
        }
    }

    // ---- phase 1: A and B ----
    {
        ull accA[16], accB[16];
#pragma unroll
        for (int j = 0; j < 16; j++) {
            accA[j] = *reinterpret_cast<const ull*>(sbe1 + 2 * j);
            accB[j] = pack2(0.0f, 0.0f);
        }
#pragma unroll
        for (int i = 0; i < 32; i++) {
            ull ev = pack2(x[i], x[i]);
            const ulonglong2* wa = reinterpret_cast<const ulonglong2*>(sW1 + i * 32);
            const ulonglong2* wb = reinterpret_cast<const ulonglong2*>(sW1 + (32 + i) * 32);
#pragma unroll
            for (int k = 0; k < 8; k++) {
                ulonglong2 w = wa[k];
                accA[2*k]   = fma2(ev, w.x, accA[2*k]);
                accA[2*k+1] = fma2(ev, w.y, accA[2*k+1]);
            }
#pragma unroll
            for (int k = 0; k < 8; k++) {
                ulonglong2 w = wb[k];
                accB[2*k]   = fma2(ev, w.x, accB[2*k]);
                accB[2*k+1] = fma2(ev, w.y, accB[2*k+1]);
            }
        }
        ulonglong2* pA = reinterpret_cast<ulonglong2*>(g_A + (size_t)n * 32);
        ulonglong2* pB = reinterpret_cast<ulonglong2*>(g_B + (size_t)n * 32);
#pragma unroll
        for (int k = 0; k < 8; k++) pA[k] = make_ulonglong2(accA[2*k], accA[2*k+1]);
#pragma unroll
        for (int k = 0; k < 8; k++) pB[k] = make_ulonglong2(accB[2*k], accB[2*k+1]);
    }

    // ---- phase 2: C ----
    {
        ull accC[32];
#pragma unroll
        for (int j = 0; j < 32; j++)
            accC[j] = *reinterpret_cast<const ull*>(sbn1 + 2 * j);
#pragma unroll
        for (int i = 0; i < 32; i++) {
            ull ev = pack2(x[i], x[i]);
            const ulonglong2* wc = reinterpret_cast<const ulonglong2*>(sWn + i * 64);
#pragma unroll
            for (int k = 0; k < 16; k++) {
                ulonglong2 w = wc[k];
                accC[2*k]   = fma2(ev, w.x, accC[2*k]);
                accC[2*k+1] = fma2(ev, w.y, accC[2*k+1]);
            }
        }
        ulonglong2* pC = reinterpret_cast<ulonglong2*>(g_C + (size_t)n * 64);
#pragma unroll
        for (int k = 0; k < 16; k++) pC[k] = make_ulonglong2(accC[2*k], accC[2*k+1]);
    }
}

// ======= edge kernel (R13 structure): async C at top, fused A+B gather =====
__global__ void __launch_bounds__(128, 3) mpn_edge_kernel(
    const float* __restrict__ x_edge,
    const int* __restrict__ src, const int* __restrict__ dst,
    const float* __restrict__ Wn2,
    float* __restrict__ out_nm, float* __restrict__ out_em)
{
    extern __shared__ char smem[];
    const uint32_t smem_base = smem_u32(smem);
    const int t = threadIdx.x;
    const int wid = t >> 5;
    const int lane = t & 31;

    // ---- hoist Wn2 B-fragments (bf16 hi/lo) into registers, once ----
    const int col = lane >> 2;          // n within 8-col group
    const int krow = lane & 3;          // k-pair row within quad
    uint32_t Bh[4][4][2], Bl[4][4][2];
#pragma unroll
    for (int kt = 0; kt < 4; kt++) {
#pragma unroll
        for (int nt = 0; nt < 4; nt++) {
            int n = nt * 8 + col;
            int kp0 = kt * 8 + krow;
            int kp1 = kp0 + 4;
            float w00 = Wn2[(2 * kp0) * 32 + n];
            float w01 = Wn2[(2 * kp0 + 1) * 32 + n];
            float w10 = Wn2[(2 * kp1) * 32 + n];
            float w11 = Wn2[(2 * kp1 + 1) * 32 + n];
            uint32_t u00 = __float_as_uint(w00), u01 = __float_as_uint(w01);
            uint32_t u10 = __float_as_uint(w10), u11 = __float_as_uint(w11);
            Bh[kt][nt][0] = __byte_perm(u00, u01, 0x7632);
            Bh[kt][nt][1] = __byte_perm(u10, u11, 0x7632);
            float l00 = w00 - __uint_as_float(u00 & 0xFFFF0000u);
            float l01 = w01 - __uint_as_float(u01 & 0xFFFF0000u);
            float l10 = w10 - __uint_as_float(u10 & 0xFFFF0000u);
            float l11 = w11 - __uint_as_float(u11 & 0xFFFF0000u);
            uint32_t p0, p1;
            asm("cvt.rn.bf16x2.f32 %0, %1, %2;" : "=r"(p0) : "f"(l01), "f"(l00));
            asm("cvt.rn.bf16x2.f32 %0, %1, %2;" : "=r"(p1) : "f"(l11), "f"(l10));
            Bl[kt][nt][0] = p0;
            Bl[kt][nt][1] = p1;
        }
    }

    // epilogue bias pairs: cols nt*8 + krow*2, +1
    float2 bias[4];
#pragma unroll
    for (int nt = 0; nt < 4; nt++)
        bias[nt] = make_float2(c_bn2[nt * 8 + krow * 2], c_bn2[nt * 8 + krow * 2 + 1]);

    char* wbuf = smem + wid * W_SIZE;
    const uint32_t wbuf_u = smem_base + wid * W_SIZE;
    const uint32_t a_hi_base = wbuf_u + W_GA;
    const uint32_t a_lo_base = wbuf_u + W_GB;
    const uint32_t lds_lane_off = (uint32_t)(lane & 15) * A_STRIDE + (uint32_t)(lane >> 4) * 16;
    const int sub = lane >> 3;          // 0..3 : which edge within a gather instr
    const int qe  = lane & 7;           // 0..7 : 16B chunk within a 128B row

    const int e_base = blockIdx.x * NITER * 128 + wid * 32 + lane;
    int s_cur = src[e_base];
    int d_cur = dst[e_base];

    for (int it = 0; it < NITER; it++) {
        const int e = e_base + it * 128;
        const int s = s_cur;
        const int d = d_cur;

        // ======== C gather via cp.async (needed only at layer 3) ========
#pragma unroll
        for (int j = 0; j < 16; j++) {
            int c = 4 * j + sub;
            int eloc = c >> 1, half = c & 1;
            int dn = __shfl_sync(0xFFFFFFFFu, d, eloc);
            const float* gp = g_C + (size_t)dn * 64 + half * 32 + qe * 4;
            uint32_t sp = wbuf_u + W_GC + eloc * C_STRIDE + half * 128 + qe * 16;
            cp_async16(sp, gp);
        }
        cp_commit();

        // ======== A+B fused gather (consumed at layer 1) ========
#pragma unroll
        for (int j = 0; j < 8; j++) {
            int eloc = 4 * j + sub;
            int dn = __shfl_sync(0xFFFFFFFFu, d, eloc);
            int sn = __shfl_sync(0xFFFFFFFFu, s, eloc);
            ulonglong2 va = *reinterpret_cast<const ulonglong2*>(g_A + (size_t)dn * 32 + qe * 4);
            ulonglong2 vb = *reinterpret_cast<const ulonglong2*>(g_B + (size_t)sn * 32 + qe * 4);
            ulonglong2 r;
            r.x = add2(va.x, vb.x);
            r.y = add2(va.y, vb.y);
            *reinterpret_cast<ulonglong2*>(wbuf + W_GA + eloc * A_STRIDE + qe * 16) = r;
        }

        // xe load + next-iter index prefetch (latency off critical path)
        float xe[6];
        {
            const float2* pe = reinterpret_cast<const float2*>(x_edge + (size_t)e * 6);
            float2 a = pe[0], b = pe[1], c = pe[2];
            xe[0]=a.x; xe[1]=a.y; xe[2]=b.x; xe[3]=b.y; xe[4]=c.x; xe[5]=c.y;
        }
        int s_nxt = 0, d_nxt = 0;
        if (it + 1 < NITER) {
            s_nxt = src[e + 128];
            d_nxt = dst[e + 128];
        }
        __syncwarp();

        // ======== layer 1: acc1 = (A[d]+B[s]) + xe @ We1[64:70] ========
        ull acc1[16];
        {
            const ulonglong2* ra = reinterpret_cast<const ulonglong2*>(wbuf + W_GA + lane * A_STRIDE);
#pragma unroll
            for (int k = 0; k < 8; k++) {
                ulonglong2 a = ra[k];
                acc1[2*k]   = a.x;
                acc1[2*k+1] = a.y;
            }
        }
#pragma unroll
        for (int i = 0; i < 6; i++) {
            ull ev = pack2(xe[i], xe[i]);
            const ulonglong2* w = reinterpret_cast<const ulonglong2*>(c_We1t + i * 32);
#pragma unroll
            for (int k = 0; k < 8; k++) {
                ulonglong2 wp = w[k];
                acc1[2*k]   = fma2(ev, wp.x, acc1[2*k]);
                acc1[2*k+1] = fma2(ev, wp.y, acc1[2*k+1]);
            }
        }
        float h1[32];
#pragma unroll
        for (int j = 0; j < 16; j++) relu2(acc1[j], h1[2*j], h1[2*j+1]);

        // ======== layer 2: em = relu(h1 @ We2 + be2), 6 accumulator chains ===
        ull acc2a[3], acc2b[3];
#pragma unroll
        for (int j = 0; j < 3; j++) {
            acc2a[j] = *reinterpret_cast<const ull*>(c_be2 + 2 * j);
            acc2b[j] = pack2(0.0f, 0.0f);
        }
#pragma unroll
        for (int i = 0; i < 16; i++) {
            const ull* wA = reinterpret_cast<const ull*>(c_We2 + i * 6);
            const ull* wB = reinterpret_cast<const ull*>(c_We2 + (16 + i) * 6);
            ull evA = pack2(h1[i], h1[i]);
            ull evB = pack2(h1[16 + i], h1[16 + i]);
            acc2a[0] = fma2(evA, wA[0], acc2a[0]);
            acc2a[1] = fma2(evA, wA[1], acc2a[1]);
            acc2a[2] = fma2(evA, wA[2], acc2a[2]);
            acc2b[0] = fma2(evB, wB[0], acc2b[0]);
            acc2b[1] = fma2(evB, wB[1], acc2b[1]);
            acc2b[2] = fma2(evB, wB[2], acc2b[2]);
        }
        float em[6];
#pragma unroll
        for (int j = 0; j < 3; j++) relu2(add2(acc2a[j], acc2b[j]), em[2*j], em[2*j+1]);
        {
            float2* po = reinterpret_cast<float2*>(out_em + (size_t)e * 6);
            po[0] = make_float2(em[0], em[1]);
            po[1] = make_float2(em[2], em[3]);
            po[2] = make_float2(em[4], em[5]);
        }

        // ======== wait for async C, then layer 3 ========
        cp_wait0();
        __syncwarp();

        ull emv[6];
#pragma unroll
        for (int i = 0; i < 6; i++) emv[i] = pack2(em[i], em[i]);

        const char* rowC = wbuf + W_GC + lane * C_STRIDE;
        char* rowH = wbuf + W_GA + lane * A_STRIDE;
        char* rowL = wbuf + W_GB + lane * A_STRIDE;
#pragma unroll
        for (int c = 0; c < 4; c++) {
            ull acc3[8];
            const longlong2* pc = reinterpret_cast<const longlong2*>(rowC + c * 64);
#pragma unroll
            for (int k = 0; k < 4; k++) {
                longlong2 v = pc[k];
                acc3[2*k] = (ull)v.x; acc3[2*k+1] = (ull)v.y;
            }
#pragma unroll
            for (int i = 0; i < 6; i++) {
                const ulonglong2* w = reinterpret_cast<const ulonglong2*>(c_Wn1t + i * 64 + c * 16);
#pragma unroll
                for (int k = 0; k < 4; k++) {
                    ulonglong2 wp = w[k];
                    acc3[2*k]   = fma2(emv[i], wp.x, acc3[2*k]);
                    acc3[2*k+1] = fma2(emv[i], wp.y, acc3[2*k+1]);
                }
            }
            uint32_t hi[8], lo[8];
#pragma unroll
            for (int j = 0; j < 8; j++) {
                float a, b;
                relu2(acc3[j], a, b);
                uint32_t ua = __float_as_uint(a);
                uint32_t ub = __float_as_uint(b);
                float la = a - __uint_as_float(ua & 0xFFFF0000u);
                float lb = b - __uint_as_float(ub & 0xFFFF0000u);
                hi[j] = __byte_perm(ua, ub, 0x7632);
                asm("cvt.rn.bf16x2.f32 %0, %1, %2;" : "=r"(lo[j]) : "f"(lb), "f"(la));
            }
            reinterpret_cast<uint4*>(rowH)[2*c]     = make_uint4(hi[0], hi[1], hi[2], hi[3]);
            reinterpret_cast<uint4*>(rowH)[2*c + 1] = make_uint4(hi[4], hi[5], hi[6], hi[7]);
            reinterpret_cast<uint4*>(rowL)[2*c]     = make_uint4(lo[0], lo[1], lo[2], lo[3]);
            reinterpret_cast<uint4*>(rowL)[2*c + 1] = make_uint4(lo[4], lo[5], lo[6], lo[7]);
        }
        __syncwarp();

        // ======== layer 4: C[32x32] = Ahi@(Bhi+Blo) + Alo@Bhi via mma.sync ===
        float acc[8][4];
#pragma unroll
        for (int f = 0; f < 8; f++) {
            acc[f][0] = 0.0f; acc[f][1] = 0.0f; acc[f][2] = 0.0f; acc[f][3] = 0.0f;
        }
#pragma unroll
        for (int kt = 0; kt < 4; kt++) {
            uint32_t a0[4], a1[4];
            ldsm_x4(a0, a_hi_base + lds_lane_off + kt * 32);
            ldsm_x4(a1, a_hi_base + lds_lane_off + 16 * A_STRIDE + kt * 32);
#pragma unroll
            for (int nt = 0; nt < 4; nt++) {
                mma_bf16(acc[nt],     a0, Bh[kt][nt][0], Bh[kt][nt][1]);
                mma_bf16(acc[nt],     a0, Bl[kt][nt][0], Bl[kt][nt][1]);
                mma_bf16(acc[4 + nt], a1, Bh[kt][nt][0], Bh[kt][nt][1]);
                mma_bf16(acc[4 + nt], a1, Bl[kt][nt][0], Bl[kt][nt][1]);
            }
        }
#pragma unroll
        for (int kt = 0; kt < 4; kt++) {
            uint32_t a0[4], a1[4];
            ldsm_x4(a0, a_lo_base + lds_lane_off + kt * 32);
            ldsm_x4(a1, a_lo_base + lds_lane_off + 16 * A_STRIDE + kt * 32);
#pragma unroll
            for (int nt = 0; nt < 4; nt++) {
                mma_bf16(acc[nt],     a0, Bh[kt][nt][0], Bh[kt][nt][1]);
                mma_bf16(acc[4 + nt], a1, Bh[kt][nt][0], Bh[kt][nt][1]);
            }
        }

        // ======== epilogue: bias+relu -> smem rows (overlay GC), coop scatter =
        const int r = lane >> 2;
        const int cb = krow * 2;
        char* nmbase = wbuf + W_GC;
#pragma unroll
        for (int mt = 0; mt < 2; mt++) {
#pragma unroll
            for (int nt = 0; nt < 4; nt++) {
                const float* a = acc[mt * 4 + nt];
                float v0 = fmaxf(a[0] + bias[nt].x, 0.0f);
                float v1 = fmaxf(a[1] + bias[nt].y, 0.0f);
                float v2 = fmaxf(a[2] + bias[nt].x, 0.0f);
                float v3 = fmaxf(a[3] + bias[nt].y, 0.0f);
                *reinterpret_cast<float2*>(nmbase + (mt * 16 + r) * A_STRIDE + (nt * 8 + cb) * 4)
                    = make_float2(v0, v1);
                *reinterpret_cast<float2*>(nmbase + (mt * 16 + r + 8) * A_STRIDE + (nt * 8 + cb) * 4)
                    = make_float2(v2, v3);
            }
        }
        __syncwarp();

#pragma unroll
        for (int j = 0; j < 8; j++) {
            int eloc = 4 * j + sub;
            int dn = __shfl_sync(0xFFFFFFFFu, d, eloc);
            float4 v = *reinterpret_cast<const float4*>(nmbase + eloc * A_STRIDE + qe * 16);
            asm volatile("red.global.add.v4.f32 [%0], {%1, %2, %3, %4};"
                         :: "l"(out_nm + (size_t)dn * 32 + qe * 4),
                            "f"(v.x), "f"(v.y), "f"(v.z), "f"(v.w) : "memory");
        }
        __syncwarp();   // nm smem reads done before next iter's C cp.async lands

        s_cur = s_nxt;
        d_cur = d_nxt;
    }
}

extern "C" void kernel_launch(void* const* d_in, const int* in_sizes, int n_in,
                              void* d_out, int out_size) {
    const float* x_node = (const float*)d_in[0];
    const float* x_edge = (const float*)d_in[1];
    const int*   src    = (const int*)d_in[2];
    const int*   dst    = (const int*)d_in[3];
    const float* We1    = (const float*)d_in[4];
    const float* be1    = (const float*)d_in[5];
    const float* We2    = (const float*)d_in[6];
    const float* be2    = (const float*)d_in[7];
    const float* Wn1    = (const float*)d_in[8];
    const float* bn1    = (const float*)d_in[9];
    const float* Wn2    = (const float*)d_in[10];
    const float* bn2    = (const float*)d_in[11];

    float* out    = (float*)d_out;
    float* out_nm = out;                        // [N_NODES, 32]
    float* out_em = out + (size_t)N_NODES * 32; // [N_EDGES, 6]

    cudaFuncSetAttribute(mpn_edge_kernel,
                         cudaFuncAttributeMaxDynamicSharedMemorySize, SM_TOTAL);

    // Stage small weights into constant memory (async D2D, graph-capturable).
    cudaMemcpyToSymbolAsync(c_We1t, We1 + 64 * 32, 6 * 32 * sizeof(float), 0,
                            cudaMemcpyDeviceToDevice);
    cudaMemcpyToSymbolAsync(c_We2, We2, 32 * 6 * sizeof(float), 0,
                            cudaMemcpyDeviceToDevice);
    cudaMemcpyToSymbolAsync(c_Wn1t, Wn1 + 32 * 64, 6 * 64 * sizeof(float), 0,
                            cudaMemcpyDeviceToDevice);
    cudaMemcpyToSymbolAsync(c_be2, be2, 6 * sizeof(float), 0,
                            cudaMemcpyDeviceToDevice);
    cudaMemcpyToSymbolAsync(c_bn2, bn2, 32 * sizeof(float), 0,
                            cudaMemcpyDeviceToDevice);

    cudaMemsetAsync(out_nm, 0, (size_t)N_NODES * 32 * sizeof(float));

    mpn_precompute_kernel<<<(N_NODES + 255) / 256, 256>>>(x_node, We1, be1, Wn1, bn1);

    mpn_edge_kernel<<<GRID_EDGE, 128, SM_TOTAL>>>(x_edge, src, dst, Wn2,
                                                  out_nm, out_em);
}